// round 3
// baseline (speedup 1.0000x reference)
#include <cuda_runtime.h>

#define NT1 256
#define NT2 256
#define NSTAT 54
#define MAXB 512

// scratch (static device arrays: no allocations)
__device__ float g_partials[MAXB * NSTAT];
__device__ float g_combos[10 * 64];

#define XOFF ((float)(0.16 / 2.0 + 0.0))
#define YOFF ((float)(0.16 / 2.0 - 39.68))

__device__ __forceinline__ float warp_sum(float v) {
#pragma unroll
    for (int o = 16; o; o >>= 1) v += __shfl_xor_sync(0xffffffffu, v, o);
    return v;
}

// ---------------------------------------------------------------------------
// Pass 1: four threads per pillar (slot = 4n+h). Each thread accumulates
// per-pillar base moments: A1 = sum over ALL slots of xyz, V1[4] = sum over
// valid slots, V2[10] = upper-tri second moments over valid slots.
// Group-combine via shfl xor {1,2}; group leader (h==0) expands into the 54
// global stats of the 9-channel augmented features and writes them to smem:
//   f = (x,y,z,w, x-mx, y-my, z-mz, x-cx, y-cy)
//   sum f_i f_j = V2_ij - off_i V1_j - off_j V1_i + np off_i off_j
// Block then flat-reduces the 64x54 smem matrix -> per-block partials.
// ---------------------------------------------------------------------------
__global__ void __launch_bounds__(NT1) pass1_kernel(
    const float4* __restrict__ in4, const int* __restrict__ npts,
    const int* __restrict__ coords, int P) {
    __shared__ float red[NT1 / 4][NSTAT];   // 64 x 54 floats
    __shared__ float part[4][NSTAT];
    int tid = threadIdx.x;
    int g = blockIdx.x * NT1 + tid;
    int p = g >> 2;
    int h = g & 3;
    int grp = tid >> 2;

    float a1x = 0.f, a1y = 0.f, a1z = 0.f;
    float v1[4] = {0.f, 0.f, 0.f, 0.f};
    float v2[10] = {0.f, 0.f, 0.f, 0.f, 0.f, 0.f, 0.f, 0.f, 0.f, 0.f};

    bool active = (p < P);
    int np = 1;
    float cx = 0.f, cy = 0.f;
    if (active) {
        np = npts[p];
        cx = (float)coords[p * 4 + 3] * 0.16f + XOFF;
        cy = (float)coords[p * 4 + 2] * 0.16f + YOFF;
        const float4* base = in4 + (size_t)p * 32 + h;
#pragma unroll
        for (int n = 0; n < 8; n++) {
            float4 pt = base[4 * n];
            a1x += pt.x; a1y += pt.y; a1z += pt.z;
            if (4 * n + h < np) {
                v1[0] += pt.x; v1[1] += pt.y; v1[2] += pt.z; v1[3] += pt.w;
                v2[0] = fmaf(pt.x, pt.x, v2[0]);
                v2[1] = fmaf(pt.x, pt.y, v2[1]);
                v2[2] = fmaf(pt.x, pt.z, v2[2]);
                v2[3] = fmaf(pt.x, pt.w, v2[3]);
                v2[4] = fmaf(pt.y, pt.y, v2[4]);
                v2[5] = fmaf(pt.y, pt.z, v2[5]);
                v2[6] = fmaf(pt.y, pt.w, v2[6]);
                v2[7] = fmaf(pt.z, pt.z, v2[7]);
                v2[8] = fmaf(pt.z, pt.w, v2[8]);
                v2[9] = fmaf(pt.w, pt.w, v2[9]);
            }
        }
    }
    // combine the 4 threads of the pillar group
#pragma unroll
    for (int o = 1; o <= 2; o <<= 1) {
        a1x += __shfl_xor_sync(0xffffffffu, a1x, o);
        a1y += __shfl_xor_sync(0xffffffffu, a1y, o);
        a1z += __shfl_xor_sync(0xffffffffu, a1z, o);
#pragma unroll
        for (int i = 0; i < 4; i++) v1[i] += __shfl_xor_sync(0xffffffffu, v1[i], o);
#pragma unroll
        for (int i = 0; i < 10; i++) v2[i] += __shfl_xor_sync(0xffffffffu, v2[i], o);
    }

    if (h == 0) {
        if (active) {
            float npf = (float)np;
            float rnp = 1.f / npf;
            float mx = a1x * rnp, my = a1y * rnp, mz = a1z * rnp;
            const int bi[9] = {0, 1, 2, 3, 0, 1, 2, 0, 1};
            const int sym[4][4] = {{0, 1, 2, 3}, {1, 4, 5, 6},
                                   {2, 5, 7, 8}, {3, 6, 8, 9}};
            float off[9] = {0.f, 0.f, 0.f, 0.f, mx, my, mz, cx, cy};
            float b1v[9];
#pragma unroll
            for (int i = 0; i < 9; i++) b1v[i] = v1[bi[i]];
#pragma unroll
            for (int i = 0; i < 9; i++) red[grp][i] = b1v[i] - npf * off[i];
            int k = 9;
#pragma unroll
            for (int i = 0; i < 9; i++)
#pragma unroll
                for (int j = i; j < 9; j++) {
                    red[grp][k] = v2[sym[bi[i]][bi[j]]] - off[i] * b1v[j]
                                  - off[j] * b1v[i] + npf * off[i] * off[j];
                    k++;
                }
        } else {
#pragma unroll
            for (int i = 0; i < NSTAT; i++) red[grp][i] = 0.f;
        }
    }
    __syncthreads();

    // flat block reduction: 216 threads, each sums 16 rows of one stat
    if (tid < NSTAT * 4) {
        int s = tid % NSTAT;
        int q = tid / NSTAT;   // 0..3
        float v = 0.f;
#pragma unroll
        for (int r = 0; r < 16; r++) v += red[q * 16 + r][s];
        part[q][s] = v;
    }
    __syncthreads();
    if (tid < NSTAT) {
        g_partials[blockIdx.x * NSTAT + tid] =
            part[0][tid] + part[1][tid] + part[2][tid] + part[3][tid];
    }
}

// ---------------------------------------------------------------------------
// Finalize: reduce per-block partials (54 stats x 8 reducer rows), derive
// per-channel BN mean/var from the 9x9 moment matrix, fold into collapsed
// 4-wide weight combos + per-pillar-constant coefficients + bias.
// ---------------------------------------------------------------------------
__global__ void finalize_kernel(const float* __restrict__ W,
                                const float* __restrict__ gamma,
                                const float* __restrict__ beta,
                                float invPN, int nb) {
    __shared__ float red[8][NSTAT];
    __shared__ float st[NSTAT];
    int t = threadIdx.x;  // 0..431
    int s = t % NSTAT;
    int r = t / NSTAT;    // 0..7
    if (t < NSTAT * 8) {
        float v = 0.f;
        for (int b = r; b < nb; b += 8) v += g_partials[b * NSTAT + s];
        red[r][s] = v;
    }
    __syncthreads();
    if (t < NSTAT) {
        float x = 0.f;
#pragma unroll
        for (int r2 = 0; r2 < 8; r2++) x += red[r2][t];
        st[t] = x;
    }
    __syncthreads();
    if (t < 64) {
        float wc[9];
#pragma unroll
        for (int k = 0; k < 9; k++) wc[k] = W[k * 64 + t];
        float mean = 0.f;
#pragma unroll
        for (int k = 0; k < 9; k++) mean = fmaf(st[k], wc[k], mean);
        mean *= invPN;
        float ex2 = 0.f;
        int idx = 9;
#pragma unroll
        for (int i = 0; i < 9; i++)
#pragma unroll
            for (int j = i; j < 9; j++) {
                float coef = (i == j) ? 1.f : 2.f;
                ex2 = fmaf(st[idx] * coef, wc[i] * wc[j], ex2);
                idx++;
            }
        ex2 *= invPN;
        float var = ex2 - mean * mean;
        float a = gamma[t] / sqrtf(var + 1e-3f);
        float b = beta[t] - mean * a;
        g_combos[0 * 64 + t] = a * (wc[0] + wc[4] + wc[7]);  // coeff of px
        g_combos[1 * 64 + t] = a * (wc[1] + wc[5] + wc[8]);  // coeff of py
        g_combos[2 * 64 + t] = a * (wc[2] + wc[6]);          // coeff of pz
        g_combos[3 * 64 + t] = a * wc[3];                    // coeff of pw
        g_combos[4 * 64 + t] = a * wc[4];                    // mean-x coeff
        g_combos[5 * 64 + t] = a * wc[5];
        g_combos[6 * 64 + t] = a * wc[6];
        g_combos[7 * 64 + t] = a * wc[7];                    // cx coeff
        g_combos[8 * 64 + t] = a * wc[8];                    // cy coeff
        g_combos[9 * 64 + t] = b;                            // BN bias
    }
}

// ---------------------------------------------------------------------------
// Pass 2: exactly ONE pillar per warp; lane owns channels (lane, lane+32).
// Points staged to shared, broadcast-read in the inner loop (no shfls there).
// relu/max commute: M = max_n t_n (pc-free), result = relu(M + pc), with
// masked-slot contribution relu(b) when nv < 32.
// ---------------------------------------------------------------------------
__global__ void __launch_bounds__(NT2) pass2_kernel(
    const float4* __restrict__ in4, const int* __restrict__ npts,
    const int* __restrict__ coords, float* __restrict__ out, int P) {
    __shared__ float4 tile[NT2 / 32][32];
    int lane = threadIdx.x & 31;
    int wid = threadIdx.x >> 5;
    int p = (blockIdx.x * NT2 + threadIdx.x) >> 5;
    if (p >= P) return;  // warp-uniform
    int c0 = lane, c1 = lane + 32;

    float4 pt = in4[(size_t)p * 32 + lane];
    tile[wid][lane] = pt;
    int np = npts[p];
    int cyi = coords[p * 4 + 2];
    int cxi = coords[p * 4 + 3];

    float wx0 = g_combos[c0],       wx1 = g_combos[c1];
    float wy0 = g_combos[64 + c0],  wy1 = g_combos[64 + c1];
    float wz0 = g_combos[128 + c0], wz1 = g_combos[128 + c1];
    float ww0 = g_combos[192 + c0], ww1 = g_combos[192 + c1];

    float sx = warp_sum(pt.x);
    float sy = warp_sum(pt.y);
    float sz = warp_sum(pt.z);
    __syncwarp();

    int nv = min(np, 32);
    float M0 = -3.0e38f, M1 = -3.0e38f;
#pragma unroll 4
    for (int n = 0; n < nv; n++) {
        float4 q = tile[wid][n];
        float t0 = fmaf(q.x, wx0, fmaf(q.y, wy0, fmaf(q.z, wz0, q.w * ww0)));
        float t1 = fmaf(q.x, wx1, fmaf(q.y, wy1, fmaf(q.z, wz1, q.w * ww1)));
        M0 = fmaxf(M0, t0);
        M1 = fmaxf(M1, t1);
    }

    float a40 = g_combos[256 + c0], a41 = g_combos[256 + c1];
    float a50 = g_combos[320 + c0], a51 = g_combos[320 + c1];
    float a60 = g_combos[384 + c0], a61 = g_combos[384 + c1];
    float a70 = g_combos[448 + c0], a71 = g_combos[448 + c1];
    float a80 = g_combos[512 + c0], a81 = g_combos[512 + c1];
    float b0  = g_combos[576 + c0], b1  = g_combos[576 + c1];

    float rnp = 1.0f / (float)np;
    float mx = sx * rnp, my = sy * rnp, mz = sz * rnp;
    float cx = (float)cxi * 0.16f + XOFF;
    float cy = (float)cyi * 0.16f + YOFF;
    float pc0 = b0 - fmaf(mx, a40, fmaf(my, a50, fmaf(mz, a60,
                 fmaf(cx, a70, cy * a80))));
    float pc1 = b1 - fmaf(mx, a41, fmaf(my, a51, fmaf(mz, a61,
                 fmaf(cx, a71, cy * a81))));
    float r0 = fmaxf(M0 + pc0, 0.f);
    float r1 = fmaxf(M1 + pc1, 0.f);
    if (nv < 32) {
        r0 = fmaxf(r0, fmaxf(b0, 0.f));
        r1 = fmaxf(r1, fmaxf(b1, 0.f));
    }
    out[(size_t)p * 64 + c0] = r0;
    out[(size_t)p * 64 + c1] = r1;
}

extern "C" void kernel_launch(void* const* d_in, const int* in_sizes, int n_in,
                              void* d_out, int out_size) {
    const float4* in4 = (const float4*)d_in[0];
    const int* npts = (const int*)d_in[1];
    const int* coords = (const int*)d_in[2];
    const float* W = (const float*)d_in[3];
    const float* gamma = (const float*)d_in[4];
    const float* beta = (const float*)d_in[5];
    float* out = (float*)d_out;

    int P = in_sizes[1];                 // 30000
    int N = in_sizes[0] / (P * 4);       // 32
    float invPN = 1.0f / ((float)P * (float)N);

    int nb1 = (4 * P + NT1 - 1) / NT1;   // 469 for P=30000
    if (nb1 > MAXB) nb1 = MAXB;          // (problem sizes fixed; safety clamp)
    int nb2 = (8 * P + NT2 / 32 * 32 - 1) / (NT2 / 32 * 32) ;
    nb2 = (P + (NT2 / 32) - 1) / (NT2 / 32);  // one warp per pillar: 3750

    pass1_kernel<<<nb1, NT1>>>(in4, npts, coords, P);
    finalize_kernel<<<1, NSTAT * 8>>>(W, gamma, beta, invPN, nb1);
    pass2_kernel<<<nb2, NT2>>>(in4, npts, coords, out, P);
}

// round 4
// speedup vs baseline: 1.0234x; 1.0234x over previous
#include <cuda_runtime.h>

#define NT 256
#define NSTAT 54
#define MAXB 512
#define TROW 33   // tile row stride in float4 (padded: kills STS bank conflicts)

// scratch (static device arrays: no allocations)
__device__ float g_partials[MAXB * NSTAT];
__device__ float g_combos[10 * 64];
__device__ int g_counter;
__device__ int g_flag;

#define XOFF ((float)(0.16 / 2.0 + 0.0))
#define YOFF ((float)(0.16 / 2.0 - 39.68))

__global__ void init_kernel() {
    g_counter = 0;
    g_flag = 0;
}

// ---------------------------------------------------------------------------
// Fused persistent kernel.
// Phase 1: 4 threads per pillar; load pillar points into smem tile while
//   accumulating base moments (A1 over all slots, V1/V2 over valid slots);
//   group-combine via shfl; leader expands into the 54 global BN stats:
//     f = (x,y,z,w, x-mx, y-my, z-mz, x-cx, y-cy)
//     sum f_i f_j = V2_ij - off_i V1_j - off_j V1_i + np off_i off_j
//   Block-reduce -> g_partials[bid].
// Barrier: atomic counter; LAST block reduces all partials, derives BN
//   mean/var from the 9x9 moment matrix, folds BN into collapsed 4-wide
//   weight combos + per-pillar-constant coeffs + bias -> g_combos; sets flag.
// Phase 2: one warp per pillar FROM SMEM (no global re-read); lane owns
//   channels (lane, lane+32); relu/max commute: result = relu(max_n t_n + pc),
//   with masked-slot contribution relu(b) when nv < 32.
// ---------------------------------------------------------------------------
__global__ void __launch_bounds__(NT) fused_kernel(
    const float4* __restrict__ in4, const int* __restrict__ npts,
    const int* __restrict__ coords, const float* __restrict__ W,
    const float* __restrict__ gamma, const float* __restrict__ beta,
    float* __restrict__ out, int P, int PPB, int NB, float invPN) {
    extern __shared__ char smraw[];
    float4* tile = (float4*)smraw;                    // PPB * TROW
    float4* meta = tile + PPB * TROW;                 // PPB
    float* red = (float*)(meta + PPB);                // 64 * NSTAT
    float* part = red + 64 * NSTAT;                   // 4 * NSTAT
    __shared__ int sh_last;

    int tid = threadIdx.x;
    int bid = blockIdx.x;
    int grp = tid >> 2;
    int h = tid & 3;
    int lane = tid & 31;
    int wid = tid >> 5;
    int iters = (PPB + 63) >> 6;

    // ---------------- Phase 1 ----------------
    for (int it = 0; it < iters; it++) {
        int lp = it * 64 + grp;
        int p = bid * PPB + lp;
        bool active = (lp < PPB) && (p < P);

        float a1x = 0.f, a1y = 0.f, a1z = 0.f;
        float v1[4] = {0.f, 0.f, 0.f, 0.f};
        float v2[10] = {0.f, 0.f, 0.f, 0.f, 0.f, 0.f, 0.f, 0.f, 0.f, 0.f};
        int np = 1;
        if (active) {
            np = npts[p];
            const float4* base = in4 + (size_t)p * 32 + h;
#pragma unroll
            for (int n = 0; n < 8; n++) {
                float4 pt = base[4 * n];
                tile[lp * TROW + 4 * n + h] = pt;
                a1x += pt.x; a1y += pt.y; a1z += pt.z;
                if (4 * n + h < np) {
                    v1[0] += pt.x; v1[1] += pt.y; v1[2] += pt.z; v1[3] += pt.w;
                    v2[0] = fmaf(pt.x, pt.x, v2[0]);
                    v2[1] = fmaf(pt.x, pt.y, v2[1]);
                    v2[2] = fmaf(pt.x, pt.z, v2[2]);
                    v2[3] = fmaf(pt.x, pt.w, v2[3]);
                    v2[4] = fmaf(pt.y, pt.y, v2[4]);
                    v2[5] = fmaf(pt.y, pt.z, v2[5]);
                    v2[6] = fmaf(pt.y, pt.w, v2[6]);
                    v2[7] = fmaf(pt.z, pt.z, v2[7]);
                    v2[8] = fmaf(pt.z, pt.w, v2[8]);
                    v2[9] = fmaf(pt.w, pt.w, v2[9]);
                }
            }
        }
        // combine the 4 threads of the pillar group
#pragma unroll
        for (int o = 1; o <= 2; o <<= 1) {
            a1x += __shfl_xor_sync(0xffffffffu, a1x, o);
            a1y += __shfl_xor_sync(0xffffffffu, a1y, o);
            a1z += __shfl_xor_sync(0xffffffffu, a1z, o);
#pragma unroll
            for (int i = 0; i < 4; i++)
                v1[i] += __shfl_xor_sync(0xffffffffu, v1[i], o);
#pragma unroll
            for (int i = 0; i < 10; i++)
                v2[i] += __shfl_xor_sync(0xffffffffu, v2[i], o);
        }

        if (h == 0) {
            if (active) {
                float cx = (float)coords[p * 4 + 3] * 0.16f + XOFF;
                float cy = (float)coords[p * 4 + 2] * 0.16f + YOFF;
                float npf = (float)np;
                float rnp = 1.f / npf;
                float mx = a1x * rnp, my = a1y * rnp, mz = a1z * rnp;
                meta[lp] = make_float4(mx, my, mz, npf);
                const int bi[9] = {0, 1, 2, 3, 0, 1, 2, 0, 1};
                const int sym[4][4] = {{0, 1, 2, 3}, {1, 4, 5, 6},
                                       {2, 5, 7, 8}, {3, 6, 8, 9}};
                float off[9] = {0.f, 0.f, 0.f, 0.f, mx, my, mz, cx, cy};
                float b1v[9];
#pragma unroll
                for (int i = 0; i < 9; i++) b1v[i] = v1[bi[i]];
                if (it == 0) {
#pragma unroll
                    for (int i = 0; i < 9; i++)
                        red[grp * NSTAT + i] = b1v[i] - npf * off[i];
                    int k = 9;
#pragma unroll
                    for (int i = 0; i < 9; i++)
#pragma unroll
                        for (int j = i; j < 9; j++) {
                            red[grp * NSTAT + k] =
                                v2[sym[bi[i]][bi[j]]] - off[i] * b1v[j]
                                - off[j] * b1v[i] + npf * off[i] * off[j];
                            k++;
                        }
                } else {
#pragma unroll
                    for (int i = 0; i < 9; i++)
                        red[grp * NSTAT + i] += b1v[i] - npf * off[i];
                    int k = 9;
#pragma unroll
                    for (int i = 0; i < 9; i++)
#pragma unroll
                        for (int j = i; j < 9; j++) {
                            red[grp * NSTAT + k] +=
                                v2[sym[bi[i]][bi[j]]] - off[i] * b1v[j]
                                - off[j] * b1v[i] + npf * off[i] * off[j];
                            k++;
                        }
                }
            } else if (it == 0) {
#pragma unroll
                for (int i = 0; i < NSTAT; i++) red[grp * NSTAT + i] = 0.f;
            }
        }
    }
    __syncthreads();

    // block reduce red(64 x 54) -> part(4 x 54) -> g_partials[bid]
    if (tid < NSTAT * 4) {
        int s = tid % NSTAT;
        int q = tid / NSTAT;
        float v = 0.f;
#pragma unroll
        for (int r = 0; r < 16; r++) v += red[(q * 16 + r) * NSTAT + s];
        part[q * NSTAT + s] = v;
    }
    __syncthreads();
    if (tid < NSTAT) {
        g_partials[bid * NSTAT + tid] =
            part[tid] + part[NSTAT + tid] + part[2 * NSTAT + tid] +
            part[3 * NSTAT + tid];
    }
    __threadfence();
    __syncthreads();

    // ---------------- Global barrier + finalize in last block ----------------
    if (tid == 0) {
        int t = atomicAdd(&g_counter, 1);
        sh_last = (t == NB - 1) ? 1 : 0;
    }
    __syncthreads();

    if (sh_last) {
        // reduce all block partials: part[q][s] = sum over blocks q,q+4,...
        if (tid < NSTAT * 4) {
            int s = tid % NSTAT;
            int q = tid / NSTAT;
            float v = 0.f;
            for (int b = q; b < NB; b += 4) v += g_partials[b * NSTAT + s];
            part[q * NSTAT + s] = v;
        }
        __syncthreads();
        if (tid < NSTAT) {
            red[tid] = part[tid] + part[NSTAT + tid] + part[2 * NSTAT + tid] +
                       part[3 * NSTAT + tid];
        }
        __syncthreads();
        if (tid < 64) {
            float wc[9];
#pragma unroll
            for (int k = 0; k < 9; k++) wc[k] = W[k * 64 + tid];
            float mean = 0.f;
#pragma unroll
            for (int k = 0; k < 9; k++) mean = fmaf(red[k], wc[k], mean);
            mean *= invPN;
            float ex2 = 0.f;
            int idx = 9;
#pragma unroll
            for (int i = 0; i < 9; i++)
#pragma unroll
                for (int j = i; j < 9; j++) {
                    float coef = (i == j) ? 1.f : 2.f;
                    ex2 = fmaf(red[idx] * coef, wc[i] * wc[j], ex2);
                    idx++;
                }
            ex2 *= invPN;
            float var = ex2 - mean * mean;
            float a = gamma[tid] / sqrtf(var + 1e-3f);
            float b = beta[tid] - mean * a;
            g_combos[0 * 64 + tid] = a * (wc[0] + wc[4] + wc[7]);
            g_combos[1 * 64 + tid] = a * (wc[1] + wc[5] + wc[8]);
            g_combos[2 * 64 + tid] = a * (wc[2] + wc[6]);
            g_combos[3 * 64 + tid] = a * wc[3];
            g_combos[4 * 64 + tid] = a * wc[4];
            g_combos[5 * 64 + tid] = a * wc[5];
            g_combos[6 * 64 + tid] = a * wc[6];
            g_combos[7 * 64 + tid] = a * wc[7];
            g_combos[8 * 64 + tid] = a * wc[8];
            g_combos[9 * 64 + tid] = b;
        }
        __threadfence();
        __syncthreads();
        if (tid == 0) atomicExch(&g_flag, 1);
    } else {
        if (tid == 0) {
            while (atomicAdd(&g_flag, 0) == 0) __nanosleep(64);
        }
        __syncthreads();
    }

    // ---------------- Phase 2 (from smem) ----------------
    int c0 = lane, c1 = lane + 32;
    float wx0 = g_combos[c0],       wx1 = g_combos[c1];
    float wy0 = g_combos[64 + c0],  wy1 = g_combos[64 + c1];
    float wz0 = g_combos[128 + c0], wz1 = g_combos[128 + c1];
    float ww0 = g_combos[192 + c0], ww1 = g_combos[192 + c1];
    float a40 = g_combos[256 + c0], a41 = g_combos[256 + c1];
    float a50 = g_combos[320 + c0], a51 = g_combos[320 + c1];
    float a60 = g_combos[384 + c0], a61 = g_combos[384 + c1];
    float a70 = g_combos[448 + c0], a71 = g_combos[448 + c1];
    float a80 = g_combos[512 + c0], a81 = g_combos[512 + c1];
    float b0  = g_combos[576 + c0], b1  = g_combos[576 + c1];
    float rb0 = fmaxf(b0, 0.f), rb1 = fmaxf(b1, 0.f);

    for (int lp = wid; lp < PPB; lp += NT / 32) {
        int p = bid * PPB + lp;
        if (p >= P) break;  // warp-uniform
        float4 mt = meta[lp];
        int np = (int)mt.w;
        int nv = min(np, 32);
        const float4* trow = tile + lp * TROW;
        float M0 = -3.0e38f, M1 = -3.0e38f;
#pragma unroll 4
        for (int n = 0; n < nv; n++) {
            float4 q = trow[n];
            float t0 = fmaf(q.x, wx0, fmaf(q.y, wy0, fmaf(q.z, wz0, q.w * ww0)));
            float t1 = fmaf(q.x, wx1, fmaf(q.y, wy1, fmaf(q.z, wz1, q.w * ww1)));
            M0 = fmaxf(M0, t0);
            M1 = fmaxf(M1, t1);
        }
        float cx = (float)coords[p * 4 + 3] * 0.16f + XOFF;
        float cy = (float)coords[p * 4 + 2] * 0.16f + YOFF;
        float pc0 = b0 - fmaf(mt.x, a40, fmaf(mt.y, a50, fmaf(mt.z, a60,
                     fmaf(cx, a70, cy * a80))));
        float pc1 = b1 - fmaf(mt.x, a41, fmaf(mt.y, a51, fmaf(mt.z, a61,
                     fmaf(cx, a71, cy * a81))));
        float r0 = fmaxf(M0 + pc0, 0.f);
        float r1 = fmaxf(M1 + pc1, 0.f);
        if (nv < 32) { r0 = fmaxf(r0, rb0); r1 = fmaxf(r1, rb1); }
        out[(size_t)p * 64 + c0] = r0;
        out[(size_t)p * 64 + c1] = r1;
    }
}

extern "C" void kernel_launch(void* const* d_in, const int* in_sizes, int n_in,
                              void* d_out, int out_size) {
    const float4* in4 = (const float4*)d_in[0];
    const int* npts = (const int*)d_in[1];
    const int* coords = (const int*)d_in[2];
    const float* W = (const float*)d_in[3];
    const float* gamma = (const float*)d_in[4];
    const float* beta = (const float*)d_in[5];
    float* out = (float*)d_out;

    int P = in_sizes[1];                 // 30000
    int N = in_sizes[0] / (P * 4);       // 32
    float invPN = 1.0f / ((float)P * (float)N);

    // target ~295 blocks (all co-resident: smem-limited 3 blocks/SM x 148 SMs)
    int PPB = (P + 294) / 295;           // 102 for P=30000
    int NB = (P + PPB - 1) / PPB;        // 295
    if (NB > MAXB) NB = MAXB;            // safety (fixed shapes in practice)

    size_t smem = (size_t)PPB * TROW * 16 + (size_t)PPB * 16 +
                  64 * NSTAT * 4 + 4 * NSTAT * 4 + 128;

    cudaFuncSetAttribute(fused_kernel,
                         cudaFuncAttributeMaxDynamicSharedMemorySize,
                         (int)smem);

    init_kernel<<<1, 1>>>();
    fused_kernel<<<NB, NT, smem>>>(in4, npts, coords, W, gamma, beta, out,
                                   P, PPB, NB, invPN);
}